// round 16
// baseline (speedup 1.0000x reference)
#include <cuda_runtime.h>
#include <math.h>

#define BB 64
#define S1 513
#define SS 512
#define HD 768
#define ST_START 2
#define ST_STOP 3
#define NEGINF (-1e30f)
#define IDMAP 0x03020100u

// ---- scratch ----
__device__ __align__(16) float g_feats[BB * SS * 4];
__device__ float g_logits[BB * 2];
__device__ float g_Z[BB];
__device__ float g_gold[BB];
__device__ int g_ready[BB];   // warp-completion count (0..64)
__device__ int g_blk[BB];     // block ticket (0..8)
__device__ int g_cls;         // CLS tasks done (0..64)
__device__ int g_done;        // Z/V completions (0..128)

// out layout (float32)
#define OFF_PRED   0
#define OFF_CRF    64
#define OFF_ILOSS  32832
#define OFF_CLOSS  32833
#define OFF_TAGS   32834
#define OFF_ISQA   65602

template<int N>
__device__ __forceinline__ void half_reduce(float* v, int lane, int d)
{
    bool up = (lane & d) != 0;
    #pragma unroll
    for (int k = 0; k < N; k++) {
        float send = up ? v[k] : v[k + N];
        float recv = __shfl_xor_sync(~0u, send, d);
        v[k] = (up ? v[k + N] : v[k]) + recv;
    }
}

// ---------- helpers ----------
__device__ __forceinline__ void mp_mul(const float* A, const float* B, float* C)
{
    #pragma unroll
    for (int i = 0; i < 4; i++)
        #pragma unroll
        for (int j = 0; j < 4; j++) {
            float m = A[i*4+0] + B[0*4+j];
            m = fmaxf(m, A[i*4+1] + B[1*4+j]);
            m = fmaxf(m, A[i*4+2] + B[2*4+j]);
            m = fmaxf(m, A[i*4+3] + B[3*4+j]);
            C[i*4+j] = m;
        }
}
__device__ __forceinline__ void lin_mul(const float* A, const float* B, float* C)
{
    #pragma unroll
    for (int i = 0; i < 4; i++)
        #pragma unroll
        for (int j = 0; j < 4; j++)
            C[i*4+j] = A[i*4+0]*B[0*4+j] + A[i*4+1]*B[1*4+j]
                     + A[i*4+2]*B[2*4+j] + A[i*4+3]*B[3*4+j];
}
__device__ __forceinline__ void cp16(float* d, const float* s)
{
    #pragma unroll
    for (int t = 0; t < 16; t++) d[t] = s[t];
}
__device__ __forceinline__ void id_mp(float* M)
{
    #pragma unroll
    for (int t = 0; t < 16; t++) M[t] = NEGINF;
    M[0] = M[5] = M[10] = M[15] = 0.f;
}
__device__ __forceinline__ void renorm16(float* M, float& logacc)
{
    float m = M[0];
    #pragma unroll
    for (int t = 1; t < 16; t++) m = fmaxf(m, M[t]);
    float inv = 1.0f / m;
    #pragma unroll
    for (int t = 0; t < 16; t++) M[t] *= inv;
    logacc += __logf(m);
}
__device__ __forceinline__ unsigned compose(unsigned f, unsigned h)
{
    unsigned r = 0;
    #pragma unroll
    for (int x = 0; x < 4; x++) {
        unsigned hx = (h >> (8 * x)) & 3u;
        unsigned fx = (f >> (8 * hx)) & 3u;
        r |= fx << (8 * x);
    }
    return r;
}

// =====================================================================
// Single fused kernel, 512 blocks x 256 threads.
// Block (b, r): produces feats row-groups r*8..r*8+7 for batch b, then
// takes a per-batch ticket; last finishers become the CRF consumers.
// =====================================================================
__global__ void __launch_bounds__(256, 2) k_all(
        const float* __restrict__ emb, const int* __restrict__ asl,
        const int* __restrict__ isqa_in,
        const float* __restrict__ fc2W, const float* __restrict__ fc2b,
        const float* __restrict__ crfW, const float* __restrict__ crfb,
        const float* __restrict__ trans, float* out)
{
    int tid = threadIdx.x;
    int lane = tid & 31, wid = tid >> 5;
    int b = blockIdx.x >> 3;
    int r = blockIdx.x & 7;

    __shared__ float sW[8][16];
    __shared__ float sWpre[8][16];
    __shared__ float zl[8];
    __shared__ float sg[8];
    __shared__ unsigned sMv[8];
    __shared__ int s_last;
    __shared__ int s_ticket;

    // =================== produce feats (8 warps x 8 rows) ===================
    {
        int g = r * 8 + wid;   // 0..63
        const float4* e4 = reinterpret_cast<const float4*>(emb)
                         + (size_t)(b * S1 + 1 + g * 8) * (HD / 4);
        const float4* wp = reinterpret_cast<const float4*>(crfW);
        float v[32];
        #pragma unroll
        for (int t = 0; t < 32; t++) v[t] = 0.f;
        #pragma unroll
        for (int k = 0; k < 6; k++) {
            int idx = k * 32 + lane;
            float4 w0 = wp[idx];
            float4 w1 = wp[192 + idx];
            float4 w2 = wp[384 + idx];
            float4 w3 = wp[576 + idx];
            #pragma unroll
            for (int rr = 0; rr < 8; rr++) {
                float4 e = e4[rr * 192 + idx];
                v[rr*4+0] += e.x * w0.x + e.y * w0.y + e.z * w0.z + e.w * w0.w;
                v[rr*4+1] += e.x * w1.x + e.y * w1.y + e.z * w1.z + e.w * w1.w;
                v[rr*4+2] += e.x * w2.x + e.y * w2.y + e.z * w2.z + e.w * w2.w;
                v[rr*4+3] += e.x * w3.x + e.y * w3.y + e.z * w3.z + e.w * w3.w;
            }
        }
        half_reduce<16>(v, lane, 16);
        half_reduce<8>(v, lane, 8);
        half_reduce<4>(v, lane, 4);
        half_reduce<2>(v, lane, 2);
        half_reduce<1>(v, lane, 1);
        g_feats[(b * SS + g * 8) * 4 + lane] = v[0] + __ldg(&crfb[lane & 3]);
        __threadfence();
        __syncwarp();
        if (lane == 0) atomicAdd(&g_ready[b], 1);
    }

    // =================== dynamic role ticket ===================
    __syncthreads();
    if (tid == 0) s_ticket = atomicAdd(&g_blk[b], 1);
    __syncthreads();
    int ticket = s_ticket;

    if (ticket < 5) return;

    if (ticket == 5) {
        // ---------------- CLS logits (warp 0 only) ----------------
        if (wid == 0) {
            const float4* e4 = reinterpret_cast<const float4*>(emb)
                             + (size_t)(b * S1) * (HD / 4);
            const float4* w0 = reinterpret_cast<const float4*>(fc2W);
            const float4* w1 = w0 + (HD / 4);
            float a0 = 0.f, a1 = 0.f;
            #pragma unroll
            for (int k = 0; k < 6; k++) {
                int idx = k * 32 + lane;
                float4 e = e4[idx];
                float4 x = w0[idx];
                float4 y = w1[idx];
                a0 += e.x * x.x + e.y * x.y + e.z * x.z + e.w * x.w;
                a1 += e.x * y.x + e.y * y.y + e.z * y.z + e.w * y.w;
            }
            #pragma unroll
            for (int off = 16; off; off >>= 1) {
                a0 += __shfl_xor_sync(~0u, a0, off);
                a1 += __shfl_xor_sync(~0u, a1, off);
            }
            if (lane == 0) {
                g_logits[b * 2 + 0] = a0 + fc2b[0];
                g_logits[b * 2 + 1] = a1 + fc2b[1];
                __threadfence();
                atomicAdd(&g_cls, 1);
            }
        }
        return;
    }

    // =================== CRF roles ===================
    bool vit = (ticket == 6);

    // ticket 6 waits for the one remaining block; ticket 7 is already ready
    if (vit) {
        if (tid == 0) {
            while (atomicAdd(&g_ready[b], 0) < 64) __nanosleep(32);
        }
        __syncthreads();
    }
    __threadfence();

    const float4* F4 = reinterpret_cast<const float4*>(g_feats) + b * SS;
    const int* tg = asl + b * S1 + 1;

    if (!vit) {
        // ================= Z + gold =================
        float4 fA = F4[tid * 2];
        float4 fB = F4[tid * 2 + 1];
        float4 fg0 = F4[tid];
        float4 fg1 = F4[256 + tid];
        int tcg0 = tg[tid], tcg1 = tg[256 + tid];
        int tpg0 = (tid > 0) ? tg[tid - 1] : 0;
        int tpg1 = tg[255 + tid];

        float T[16];
        #pragma unroll
        for (int t = 0; t < 16; t++) T[t] = __ldg(&trans[t]);

        // gold
        float gpart = 0.f;
        {
            int i = tid;
            gpart += tcg0 ? fg0.y : fg0.x;
            if (i == 0) gpart += tcg0 ? T[ST_START*4+1] : T[ST_START*4+0];
            else gpart += tpg0 ? (tcg0 ? T[5] : T[4]) : (tcg0 ? T[1] : T[0]);
            i = 256 + tid;
            gpart += tcg1 ? fg1.y : fg1.x;
            gpart += tpg1 ? (tcg1 ? T[5] : T[4]) : (tcg1 ? T[1] : T[0]);
            if (i == SS - 1) gpart += tcg1 ? T[1*4+ST_STOP] : T[0*4+ST_STOP];
        }
        #pragma unroll
        for (int off = 16; off; off >>= 1)
            gpart += __shfl_xor_sync(~0u, gpart, off);
        if (lane == 0) sg[wid] = gpart;

        // Z: local product of 2 matrices
        float E[16];
        #pragma unroll
        for (int t = 0; t < 16; t++) E[t] = __expf(T[t]);

        float M[16];
        #pragma unroll
        for (int t = 0; t < 16; t++) M[t] = 0.f;
        M[0] = M[5] = M[10] = M[15] = 1.f;
        float logacc = 0.f;

        #pragma unroll
        for (int k = 0; k < 2; k++) {
            int s = tid * 2 + k;
            if (s > 0) {
                float4 f = k ? fB : fA;
                float ef[4] = {__expf(f.x), __expf(f.y), __expf(f.z), __expf(f.w)};
                float C[16];
                #pragma unroll
                for (int i = 0; i < 4; i++)
                    #pragma unroll
                    for (int j = 0; j < 4; j++)
                        C[i*4+j] = (M[i*4+0]*E[0*4+j] + M[i*4+1]*E[1*4+j]
                                  + M[i*4+2]*E[2*4+j] + M[i*4+3]*E[3*4+j]) * ef[j];
                cp16(M, C);
            }
        }
        renorm16(M, logacc);

        #pragma unroll
        for (int d = 1; d < 32; d <<= 1) {
            float O[16];
            #pragma unroll
            for (int t = 0; t < 16; t++) O[t] = __shfl_xor_sync(~0u, M[t], d);
            float ol = __shfl_xor_sync(~0u, logacc, d);
            float C[16];
            if (lane & d) lin_mul(O, M, C);
            else          lin_mul(M, O, C);
            cp16(M, C);
            logacc += ol;
            if (d & 0x0A) renorm16(M, logacc);
        }
        renorm16(M, logacc);
        if (lane == 0) {
            #pragma unroll
            for (int t = 0; t < 16; t++) sW[wid][t] = M[t];
            zl[wid] = logacc;
        }
        __syncthreads();

        // warp 0: ordered log-tree product of the 8 warp aggregates
        if (wid == 0 && lane < 8) {
            float A[16];
            #pragma unroll
            for (int t = 0; t < 16; t++) A[t] = sW[lane][t];
            float la = zl[lane];
            float gsum = sg[lane];
            #pragma unroll
            for (int d = 1; d < 8; d <<= 1) {
                float O[16];
                #pragma unroll
                for (int t = 0; t < 16; t++) O[t] = __shfl_down_sync(0xFFu, A[t], d);
                float ol = __shfl_down_sync(0xFFu, la, d);
                float og = __shfl_down_sync(0xFFu, gsum, d);
                if ((lane & (2 * d - 1)) == 0) {
                    float C[16];
                    lin_mul(A, O, C);
                    cp16(A, C);
                    la += ol;
                    renorm16(A, la);
                    gsum += og;
                }
            }
            if (lane == 0) {
                g_gold[b] = gsum;
                float4 f0 = F4[0];
                float v0[4] = {__expf(f0.x)*E[ST_START*4+0], __expf(f0.y)*E[ST_START*4+1],
                               __expf(f0.z)*E[ST_START*4+2], __expf(f0.w)*E[ST_START*4+3]};
                float zs = 0.f;
                #pragma unroll
                for (int j = 0; j < 4; j++) {
                    float vj = v0[0]*A[0*4+j] + v0[1]*A[1*4+j]
                             + v0[2]*A[2*4+j] + v0[3]*A[3*4+j];
                    zs += vj * E[j*4+ST_STOP];
                }
                g_Z[b] = __logf(zs) + la;
            }
        }
    } else {
        // ================= viterbi =================
        float4 ff[2];
        ff[0] = F4[tid * 2];
        ff[1] = F4[tid * 2 + 1];
        float4 f0 = F4[0];
        int tag0 = tg[tid], tag1 = tg[256 + tid];

        float T[16];
        #pragma unroll
        for (int t = 0; t < 16; t++) T[t] = __ldg(&trans[t]);

        out[OFF_TAGS + b * SS + tid] = (float)tag0;
        out[OFF_TAGS + b * SS + 256 + tid] = (float)tag1;

        // local max-plus product (A_0 := identity)
        float P[16];
        id_mp(P);
        #pragma unroll
        for (int k = 0; k < 2; k++) {
            int s = tid * 2 + k;
            if (s > 0) {
                float4 f = ff[k];
                float C[16];
                #pragma unroll
                for (int i = 0; i < 4; i++) {
                    float m0 = fmaxf(fmaxf(P[i*4+0] + T[0],  P[i*4+1] + T[4]),
                                     fmaxf(P[i*4+2] + T[8],  P[i*4+3] + T[12]));
                    float m1 = fmaxf(fmaxf(P[i*4+0] + T[1],  P[i*4+1] + T[5]),
                                     fmaxf(P[i*4+2] + T[9],  P[i*4+3] + T[13]));
                    float m2 = fmaxf(fmaxf(P[i*4+0] + T[2],  P[i*4+1] + T[6]),
                                     fmaxf(P[i*4+2] + T[10], P[i*4+3] + T[14]));
                    float m3 = fmaxf(fmaxf(P[i*4+0] + T[3],  P[i*4+1] + T[7]),
                                     fmaxf(P[i*4+2] + T[11], P[i*4+3] + T[15]));
                    C[i*4+0] = m0 + f.x; C[i*4+1] = m1 + f.y;
                    C[i*4+2] = m2 + f.z; C[i*4+3] = m3 + f.w;
                }
                cp16(P, C);
            }
        }

        // warp inclusive prefix scan
        float S[16];
        cp16(S, P);
        #pragma unroll
        for (int d = 1; d < 32; d <<= 1) {
            float U[16];
            #pragma unroll
            for (int t = 0; t < 16; t++) U[t] = __shfl_up_sync(~0u, S[t], d);
            if (lane >= d) {
                float C[16];
                mp_mul(U, S, C);
                cp16(S, C);
            }
        }
        if (lane == 31) {
            #pragma unroll
            for (int t = 0; t < 16; t++) sW[wid][t] = S[t];
        }
        __syncthreads();

        if (wid == 0 && lane < 8) {
            float A[16];
            #pragma unroll
            for (int t = 0; t < 16; t++) A[t] = sW[lane][t];
            #pragma unroll
            for (int d = 1; d < 8; d <<= 1) {
                float U[16];
                #pragma unroll
                for (int t = 0; t < 16; t++) U[t] = __shfl_up_sync(0xFFu, A[t], d);
                if (lane >= d) {
                    float C[16];
                    mp_mul(U, A, C);
                    cp16(A, C);
                }
            }
            float X[16];
            #pragma unroll
            for (int t = 0; t < 16; t++) X[t] = __shfl_up_sync(0xFFu, A[t], 1);
            if (lane == 0) id_mp(X);
            #pragma unroll
            for (int t = 0; t < 16; t++) sWpre[lane][t] = X[t];
        }
        __syncthreads();

        float Sx[16];
        #pragma unroll
        for (int t = 0; t < 16; t++) Sx[t] = __shfl_up_sync(~0u, S[t], 1);
        if (lane == 0) id_mp(Sx);
        float Epre[16];
        {
            float R[16];
            #pragma unroll
            for (int t = 0; t < 16; t++) R[t] = sWpre[wid][t];
            mp_mul(R, Sx, Epre);
        }

        float d0[4] = {f0.x + T[ST_START*4+0], f0.y + T[ST_START*4+1],
                       f0.z + T[ST_START*4+2], f0.w + T[ST_START*4+3]};
        float v[4];
        #pragma unroll
        for (int j = 0; j < 4; j++) {
            float m = d0[0] + Epre[0*4+j];
            m = fmaxf(m, d0[1] + Epre[1*4+j]);
            m = fmaxf(m, d0[2] + Epre[2*4+j]);
            m = fmaxf(m, d0[3] + Epre[3*4+j]);
            v[j] = m;
        }
        unsigned bp[2];
        #pragma unroll
        for (int k = 0; k < 2; k++) {
            int s = tid * 2 + k;
            bp[k] = IDMAP;
            if (s > 0) {
                float4 f = ff[k];
                float fj[4] = {f.x, f.y, f.z, f.w};
                float nv[4];
                unsigned bpk = 0;
                #pragma unroll
                for (int j = 0; j < 4; j++) {
                    float m = v[0] + T[0*4+j]; unsigned id = 0;
                    float c1 = v[1] + T[1*4+j]; if (c1 > m) { m = c1; id = 1; }
                    float c2 = v[2] + T[2*4+j]; if (c2 > m) { m = c2; id = 2; }
                    float c3 = v[3] + T[3*4+j]; if (c3 > m) { m = c3; id = 3; }
                    nv[j] = m + fj[j];
                    bpk |= id << (8 * j);
                }
                v[0] = nv[0]; v[1] = nv[1]; v[2] = nv[2]; v[3] = nv[3];
                bp[k] = bpk;
            }
        }
        if (tid == 255) {
            float w0 = v[0] + T[0*4+ST_STOP]; int id = 0; float m = w0;
            float w1 = v[1] + T[1*4+ST_STOP]; if (w1 > m) { m = w1; id = 1; }
            float w2 = v[2] + T[2*4+ST_STOP]; if (w2 > m) { m = w2; id = 2; }
            float w3 = v[3] + T[3*4+ST_STOP]; if (w3 > m) { m = w3; id = 3; }
            s_last = id;
        }

        unsigned Mm = compose(bp[0], bp[1]);
        unsigned Sm = Mm;
        #pragma unroll
        for (int d = 1; d < 32; d <<= 1) {
            unsigned dn = __shfl_down_sync(~0u, Sm, d);
            if (lane + d < 32) Sm = compose(Sm, dn);
        }
        unsigned Em = __shfl_down_sync(~0u, Sm, 1);
        if (lane == 31) Em = IDMAP;
        if (lane == 0) sMv[wid] = Sm;
        __syncthreads();

        unsigned X = IDMAP;
        #pragma unroll
        for (int w2 = 0; w2 < 8; w2++)
            if (w2 > wid) X = compose(X, sMv[w2]);
        unsigned Efull = compose(Em, X);
        int last = s_last;
        int t1 = (Efull >> (8 * last)) & 3;
        int t0 = (bp[1] >> (8 * t1)) & 3;
        float* po = out + OFF_CRF + b * SS + tid * 2;
        po[1] = (float)t1;
        po[0] = (float)t0;
    }

    // ---------- finalize (128th Z/V completion) + resets ----------
    __syncthreads();
    __threadfence();
    if (wid == 0) {
        int dticket = 0;
        if (lane == 0) dticket = atomicAdd(&g_done, 1);
        dticket = __shfl_sync(~0u, dticket, 0);
        if (dticket == 127) {
            if (lane == 0) {
                while (atomicAdd(&g_cls, 0) < 64) __nanosleep(32);
            }
            __syncwarp();
            __threadfence();
            float il = 0.f, cl = 0.f;
            #pragma unroll
            for (int q = 0; q < 2; q++) {
                int bi = lane * 2 + q;       // 0..63
                float l0 = g_logits[bi * 2 + 0];
                float l1 = g_logits[bi * 2 + 1];
                float m = fmaxf(l0, l1);
                float lse = m + __logf(__expf(l0 - m) + __expf(l1 - m));
                int iq = isqa_in[bi];
                il += lse - (iq ? l1 : l0);
                cl += g_Z[bi] - g_gold[bi];
                out[OFF_PRED + bi] = (l1 > l0) ? 1.0f : 0.0f;
                out[OFF_ISQA + bi] = (float)iq;
                g_ready[bi] = 0;
                g_blk[bi] = 0;
            }
            #pragma unroll
            for (int off = 16; off; off >>= 1) {
                il += __shfl_xor_sync(~0u, il, off);
                cl += __shfl_xor_sync(~0u, cl, off);
            }
            if (lane == 0) {
                out[OFF_ILOSS] = il * (1.0f / BB);
                out[OFF_CLOSS] = cl * (1.0f / BB);
                g_cls = 0;
                g_done = 0;
            }
        }
    }
}

extern "C" void kernel_launch(void* const* d_in, const int* in_sizes, int n_in,
                              void* d_out, int out_size)
{
    const float* emb  = (const float*)d_in[0];
    const int*   asl  = (const int*)d_in[1];
    const int*   isqa = (const int*)d_in[2];
    const float* fc2W = (const float*)d_in[3];
    const float* fc2b = (const float*)d_in[4];
    const float* crfW = (const float*)d_in[5];
    const float* crfb = (const float*)d_in[6];
    const float* trans = (const float*)d_in[7];
    float* out = (float*)d_out;

    k_all<<<BB * 8, 256>>>(emb, asl, isqa, fc2W, fc2b,
                           crfW, crfb, trans, out);
}

// round 17
// speedup vs baseline: 1.0769x; 1.0769x over previous
#include <cuda_runtime.h>
#include <math.h>

#define BB 64
#define S1 513
#define SS 512
#define HD 768
#define ST_START 2
#define ST_STOP 3
#define NEGINF (-1e30f)
#define IDMAP 0x03020100u

#define FEATS_BLOCKS 520   // 520*8 = 4160 = 64*65 producer warps

// ---- scratch ----
__device__ __align__(16) float g_feats[BB * SS * 4];
__device__ float g_logits[BB * 2];
__device__ float g_Z[BB];
__device__ float g_gold[BB];
__device__ int g_ready[BB];   // zero-init; reset by finalize winner
__device__ int g_done;        // zero-init; reset by finalize winner

// out layout (float32)
#define OFF_PRED   0
#define OFF_CRF    64
#define OFF_ILOSS  32832
#define OFF_CLOSS  32833
#define OFF_TAGS   32834
#define OFF_ISQA   65602

template<int N>
__device__ __forceinline__ void half_reduce(float* v, int lane, int d)
{
    bool up = (lane & d) != 0;
    #pragma unroll
    for (int k = 0; k < N; k++) {
        float send = up ? v[k] : v[k + N];
        float recv = __shfl_xor_sync(~0u, send, d);
        v[k] = (up ? v[k + N] : v[k]) + recv;
    }
}

// ---------- helpers ----------
__device__ __forceinline__ void mp_mul(const float* A, const float* B, float* C)
{
    #pragma unroll
    for (int i = 0; i < 4; i++)
        #pragma unroll
        for (int j = 0; j < 4; j++) {
            float m = A[i*4+0] + B[0*4+j];
            m = fmaxf(m, A[i*4+1] + B[1*4+j]);
            m = fmaxf(m, A[i*4+2] + B[2*4+j]);
            m = fmaxf(m, A[i*4+3] + B[3*4+j]);
            C[i*4+j] = m;
        }
}
__device__ __forceinline__ void lin_mul(const float* A, const float* B, float* C)
{
    #pragma unroll
    for (int i = 0; i < 4; i++)
        #pragma unroll
        for (int j = 0; j < 4; j++)
            C[i*4+j] = A[i*4+0]*B[0*4+j] + A[i*4+1]*B[1*4+j]
                     + A[i*4+2]*B[2*4+j] + A[i*4+3]*B[3*4+j];
}
__device__ __forceinline__ void cp16(float* d, const float* s)
{
    #pragma unroll
    for (int t = 0; t < 16; t++) d[t] = s[t];
}
__device__ __forceinline__ void id_mp(float* M)
{
    #pragma unroll
    for (int t = 0; t < 16; t++) M[t] = NEGINF;
    M[0] = M[5] = M[10] = M[15] = 0.f;
}
__device__ __forceinline__ void renorm16(float* M, float& logacc)
{
    float m = M[0];
    #pragma unroll
    for (int t = 1; t < 16; t++) m = fmaxf(m, M[t]);
    float inv = 1.0f / m;
    #pragma unroll
    for (int t = 0; t < 16; t++) M[t] *= inv;
    logacc += __logf(m);
}
__device__ __forceinline__ unsigned compose(unsigned f, unsigned h)
{
    unsigned r = 0;
    #pragma unroll
    for (int x = 0; x < 4; x++) {
        unsigned hx = (h >> (8 * x)) & 3u;
        unsigned fx = (f >> (8 * hx)) & 3u;
        r |= fx << (8 * x);
    }
    return r;
}

// =====================================================================
// Fused kernel. blockIdx < FEATS_BLOCKS: feats producers (8 warps).
// blockIdx >= FEATS_BLOCKS: CRF consumers (128 blocks; scheduled LAST).
// =====================================================================
__global__ void __launch_bounds__(256, 2) k_all(
        const float* __restrict__ emb, const int* __restrict__ asl,
        const int* __restrict__ isqa_in,
        const float* __restrict__ fc2W, const float* __restrict__ fc2b,
        const float* __restrict__ crfW, const float* __restrict__ crfb,
        const float* __restrict__ trans, float* out)
{
    int tid = threadIdx.x;
    int lane = tid & 31, wid = tid >> 5;

    if (blockIdx.x < FEATS_BLOCKS) {
        // =================== feats producers ===================
        int w = blockIdx.x * 8 + wid;
        int b = w / 65;
        int g = w - b * 65;
        const float4* emb4 = reinterpret_cast<const float4*>(emb);

        if (g == 64) {
            const float4* e4 = emb4 + (size_t)(b * S1) * (HD / 4);
            const float4* w0 = reinterpret_cast<const float4*>(fc2W);
            const float4* w1 = w0 + (HD / 4);
            float a0 = 0.f, a1 = 0.f;
            #pragma unroll
            for (int k = 0; k < 6; k++) {
                int idx = k * 32 + lane;
                float4 e = e4[idx];
                float4 x = w0[idx];
                float4 y = w1[idx];
                a0 += e.x * x.x + e.y * x.y + e.z * x.z + e.w * x.w;
                a1 += e.x * y.x + e.y * y.y + e.z * y.z + e.w * y.w;
            }
            #pragma unroll
            for (int off = 16; off; off >>= 1) {
                a0 += __shfl_xor_sync(~0u, a0, off);
                a1 += __shfl_xor_sync(~0u, a1, off);
            }
            if (lane == 0) {
                g_logits[b * 2 + 0] = a0 + fc2b[0];
                g_logits[b * 2 + 1] = a1 + fc2b[1];
                __threadfence();
                atomicAdd(&g_ready[b], 1);
            }
        } else {
            const float4* e4 = emb4 + (size_t)(b * S1 + 1 + g * 8) * (HD / 4);
            const float4* wp = reinterpret_cast<const float4*>(crfW);
            float v[32];
            #pragma unroll
            for (int t = 0; t < 32; t++) v[t] = 0.f;
            #pragma unroll
            for (int k = 0; k < 6; k++) {
                int idx = k * 32 + lane;
                float4 w0 = wp[idx];
                float4 w1 = wp[192 + idx];
                float4 w2 = wp[384 + idx];
                float4 w3 = wp[576 + idx];
                #pragma unroll
                for (int r = 0; r < 8; r++) {
                    float4 e = e4[r * 192 + idx];
                    v[r*4+0] += e.x * w0.x + e.y * w0.y + e.z * w0.z + e.w * w0.w;
                    v[r*4+1] += e.x * w1.x + e.y * w1.y + e.z * w1.z + e.w * w1.w;
                    v[r*4+2] += e.x * w2.x + e.y * w2.y + e.z * w2.z + e.w * w2.w;
                    v[r*4+3] += e.x * w3.x + e.y * w3.y + e.z * w3.z + e.w * w3.w;
                }
            }
            half_reduce<16>(v, lane, 16);
            half_reduce<8>(v, lane, 8);
            half_reduce<4>(v, lane, 4);
            half_reduce<2>(v, lane, 2);
            half_reduce<1>(v, lane, 1);
            g_feats[(b * SS + g * 8) * 4 + lane] = v[0] + __ldg(&crfb[lane & 3]);
            __threadfence();
            if (lane == 0) atomicAdd(&g_ready[b], 1);
        }
        return;
    }

    // =================== CRF consumers ===================
    int cb = blockIdx.x - FEATS_BLOCKS;   // 0..127
    int b = cb & 63;
    bool vit = cb >= 64;

    __shared__ float sW[8][16];
    __shared__ float sdwb[8][4];   // delta vectors at warp boundaries (viterbi)
    __shared__ float zl[8];
    __shared__ float sg[8];
    __shared__ unsigned sMv[8];
    __shared__ int s_last;

    // wait for this batch's 65 producer warps
    if (tid == 0) {
        while (atomicAdd(&g_ready[b], 0) < 65) __nanosleep(64);
    }
    __syncthreads();
    __threadfence();

    const float4* F4 = reinterpret_cast<const float4*>(g_feats) + b * SS;

    if (!vit) {
        // issue memory early
        const int* tg = asl + b * S1 + 1;
        float4 fA = F4[tid * 2];
        float4 fB = F4[tid * 2 + 1];
        float4 fg0 = F4[tid];
        float4 fg1 = F4[256 + tid];
        int tcg0 = tg[tid], tcg1 = tg[256 + tid];
        int tpg0 = (tid > 0) ? tg[tid - 1] : 0;
        int tpg1 = tg[255 + tid];

        float T[16];
        #pragma unroll
        for (int t = 0; t < 16; t++) T[t] = __ldg(&trans[t]);

        // ---------- gold ----------
        float gpart = 0.f;
        {
            int i = tid;
            gpart += tcg0 ? fg0.y : fg0.x;
            if (i == 0) gpart += tcg0 ? T[ST_START*4+1] : T[ST_START*4+0];
            else gpart += tpg0 ? (tcg0 ? T[5] : T[4]) : (tcg0 ? T[1] : T[0]);
            i = 256 + tid;
            gpart += tcg1 ? fg1.y : fg1.x;
            gpart += tpg1 ? (tcg1 ? T[5] : T[4]) : (tcg1 ? T[1] : T[0]);
            if (i == SS - 1) gpart += tcg1 ? T[1*4+ST_STOP] : T[0*4+ST_STOP];
        }
        #pragma unroll
        for (int off = 16; off; off >>= 1)
            gpart += __shfl_xor_sync(~0u, gpart, off);
        if (lane == 0) sg[wid] = gpart;

        // ---------- Z ----------
        float E[16];
        #pragma unroll
        for (int t = 0; t < 16; t++) E[t] = __expf(T[t]);

        float M[16];
        #pragma unroll
        for (int t = 0; t < 16; t++) M[t] = 0.f;
        M[0] = M[5] = M[10] = M[15] = 1.f;
        float logacc = 0.f;

        #pragma unroll
        for (int k = 0; k < 2; k++) {
            int s = tid * 2 + k;
            if (s > 0) {
                float4 f = k ? fB : fA;
                float ef[4] = {__expf(f.x), __expf(f.y), __expf(f.z), __expf(f.w)};
                float C[16];
                #pragma unroll
                for (int i = 0; i < 4; i++)
                    #pragma unroll
                    for (int j = 0; j < 4; j++)
                        C[i*4+j] = (M[i*4+0]*E[0*4+j] + M[i*4+1]*E[1*4+j]
                                  + M[i*4+2]*E[2*4+j] + M[i*4+3]*E[3*4+j]) * ef[j];
                cp16(M, C);
            }
        }
        renorm16(M, logacc);

        #pragma unroll
        for (int d = 1; d < 32; d <<= 1) {
            float O[16];
            #pragma unroll
            for (int t = 0; t < 16; t++) O[t] = __shfl_xor_sync(~0u, M[t], d);
            float ol = __shfl_xor_sync(~0u, logacc, d);
            float C[16];
            if (lane & d) lin_mul(O, M, C);
            else          lin_mul(M, O, C);
            cp16(M, C);
            logacc += ol;
            if (d & 0x0A) renorm16(M, logacc);
        }
        renorm16(M, logacc);
        if (lane == 0) {
            #pragma unroll
            for (int t = 0; t < 16; t++) sW[wid][t] = M[t];
            zl[wid] = logacc;
        }
        __syncthreads();

        // ---- warp 0: ordered log-tree product of the 8 warp aggregates ----
        if (wid == 0 && lane < 8) {
            float A[16];
            #pragma unroll
            for (int t = 0; t < 16; t++) A[t] = sW[lane][t];
            float la = zl[lane];
            float gsum = sg[lane];
            #pragma unroll
            for (int d = 1; d < 8; d <<= 1) {
                float O[16];
                #pragma unroll
                for (int t = 0; t < 16; t++) O[t] = __shfl_down_sync(0xFFu, A[t], d);
                float ol = __shfl_down_sync(0xFFu, la, d);
                float og = __shfl_down_sync(0xFFu, gsum, d);
                if ((lane & (2 * d - 1)) == 0) {
                    float C[16];
                    lin_mul(A, O, C);
                    cp16(A, C);
                    la += ol;
                    renorm16(A, la);
                    gsum += og;
                }
            }
            if (lane == 0) {
                g_gold[b] = gsum;
                float4 f0 = F4[0];
                float v0[4] = {__expf(f0.x)*E[ST_START*4+0], __expf(f0.y)*E[ST_START*4+1],
                               __expf(f0.z)*E[ST_START*4+2], __expf(f0.w)*E[ST_START*4+3]};
                float zs = 0.f;
                #pragma unroll
                for (int j = 0; j < 4; j++) {
                    float vj = v0[0]*A[0*4+j] + v0[1]*A[1*4+j]
                             + v0[2]*A[2*4+j] + v0[3]*A[3*4+j];
                    zs += vj * E[j*4+ST_STOP];
                }
                g_Z[b] = __logf(zs) + la;
            }
        }
    } else {
        // ---------- viterbi ----------
        const int* tg = asl + b * S1 + 1;
        float4 ff[2];
        ff[0] = F4[tid * 2];
        ff[1] = F4[tid * 2 + 1];
        float4 f0 = F4[0];
        int tag0 = tg[tid], tag1 = tg[256 + tid];

        float T[16];
        #pragma unroll
        for (int t = 0; t < 16; t++) T[t] = __ldg(&trans[t]);

        out[OFF_TAGS + b * SS + tid] = (float)tag0;
        out[OFF_TAGS + b * SS + 256 + tid] = (float)tag1;

        // local max-plus product (A_0 := identity)
        float P[16];
        id_mp(P);
        #pragma unroll
        for (int k = 0; k < 2; k++) {
            int s = tid * 2 + k;
            if (s > 0) {
                float4 f = ff[k];
                float C[16];
                #pragma unroll
                for (int i = 0; i < 4; i++) {
                    float m0 = fmaxf(fmaxf(P[i*4+0] + T[0],  P[i*4+1] + T[4]),
                                     fmaxf(P[i*4+2] + T[8],  P[i*4+3] + T[12]));
                    float m1 = fmaxf(fmaxf(P[i*4+0] + T[1],  P[i*4+1] + T[5]),
                                     fmaxf(P[i*4+2] + T[9],  P[i*4+3] + T[13]));
                    float m2 = fmaxf(fmaxf(P[i*4+0] + T[2],  P[i*4+1] + T[6]),
                                     fmaxf(P[i*4+2] + T[10], P[i*4+3] + T[14]));
                    float m3 = fmaxf(fmaxf(P[i*4+0] + T[3],  P[i*4+1] + T[7]),
                                     fmaxf(P[i*4+2] + T[11], P[i*4+3] + T[15]));
                    C[i*4+0] = m0 + f.x; C[i*4+1] = m1 + f.y;
                    C[i*4+2] = m2 + f.z; C[i*4+3] = m3 + f.w;
                }
                cp16(P, C);
            }
        }

        // warp inclusive prefix scan
        float S[16];
        cp16(S, P);
        #pragma unroll
        for (int d = 1; d < 32; d <<= 1) {
            float U[16];
            #pragma unroll
            for (int t = 0; t < 16; t++) U[t] = __shfl_up_sync(~0u, S[t], d);
            if (lane >= d) {
                float C[16];
                mp_mul(U, S, C);
                cp16(S, C);
            }
        }
        if (lane == 31) {
            #pragma unroll
            for (int t = 0; t < 16; t++) sW[wid][t] = S[t];
        }
        __syncthreads();

        // thread 0: sequential delta-vector walk over warp boundaries
        if (tid == 0) {
            float dv[4] = {f0.x + T[ST_START*4+0], f0.y + T[ST_START*4+1],
                           f0.z + T[ST_START*4+2], f0.w + T[ST_START*4+3]};
            sdwb[0][0] = dv[0]; sdwb[0][1] = dv[1];
            sdwb[0][2] = dv[2]; sdwb[0][3] = dv[3];
            #pragma unroll
            for (int w2 = 0; w2 < 7; w2++) {
                float n0 = fmaxf(fmaxf(dv[0] + sW[w2][0],  dv[1] + sW[w2][4]),
                                 fmaxf(dv[2] + sW[w2][8],  dv[3] + sW[w2][12]));
                float n1 = fmaxf(fmaxf(dv[0] + sW[w2][1],  dv[1] + sW[w2][5]),
                                 fmaxf(dv[2] + sW[w2][9],  dv[3] + sW[w2][13]));
                float n2 = fmaxf(fmaxf(dv[0] + sW[w2][2],  dv[1] + sW[w2][6]),
                                 fmaxf(dv[2] + sW[w2][10], dv[3] + sW[w2][14]));
                float n3 = fmaxf(fmaxf(dv[0] + sW[w2][3],  dv[1] + sW[w2][7]),
                                 fmaxf(dv[2] + sW[w2][11], dv[3] + sW[w2][15]));
                dv[0] = n0; dv[1] = n1; dv[2] = n2; dv[3] = n3;
                sdwb[w2 + 1][0] = n0; sdwb[w2 + 1][1] = n1;
                sdwb[w2 + 1][2] = n2; sdwb[w2 + 1][3] = n3;
            }
        }
        __syncthreads();

        // per-thread delta at chunk start: dwb[wid] (x) Sx (vector-matrix)
        float Sx[16];
        #pragma unroll
        for (int t = 0; t < 16; t++) Sx[t] = __shfl_up_sync(~0u, S[t], 1);
        if (lane == 0) id_mp(Sx);
        float dw0 = sdwb[wid][0], dw1 = sdwb[wid][1];
        float dw2 = sdwb[wid][2], dw3 = sdwb[wid][3];
        float v[4];
        #pragma unroll
        for (int j = 0; j < 4; j++) {
            float m = dw0 + Sx[0*4+j];
            m = fmaxf(m, dw1 + Sx[1*4+j]);
            m = fmaxf(m, dw2 + Sx[2*4+j]);
            m = fmaxf(m, dw3 + Sx[3*4+j]);
            v[j] = m;
        }

        unsigned bp[2];
        #pragma unroll
        for (int k = 0; k < 2; k++) {
            int s = tid * 2 + k;
            bp[k] = IDMAP;
            if (s > 0) {
                float4 f = ff[k];
                float fj[4] = {f.x, f.y, f.z, f.w};
                float nv[4];
                unsigned bpk = 0;
                #pragma unroll
                for (int j = 0; j < 4; j++) {
                    float m = v[0] + T[0*4+j]; unsigned id = 0;
                    float c1 = v[1] + T[1*4+j]; if (c1 > m) { m = c1; id = 1; }
                    float c2 = v[2] + T[2*4+j]; if (c2 > m) { m = c2; id = 2; }
                    float c3 = v[3] + T[3*4+j]; if (c3 > m) { m = c3; id = 3; }
                    nv[j] = m + fj[j];
                    bpk |= id << (8 * j);
                }
                v[0] = nv[0]; v[1] = nv[1]; v[2] = nv[2]; v[3] = nv[3];
                bp[k] = bpk;
            }
        }
        if (tid == 255) {
            float w0 = v[0] + T[0*4+ST_STOP]; int id = 0; float m = w0;
            float w1 = v[1] + T[1*4+ST_STOP]; if (w1 > m) { m = w1; id = 1; }
            float w2 = v[2] + T[2*4+ST_STOP]; if (w2 > m) { m = w2; id = 2; }
            float w3 = v[3] + T[3*4+ST_STOP]; if (w3 > m) { m = w3; id = 3; }
            s_last = id;
        }

        unsigned Mm = compose(bp[0], bp[1]);
        unsigned Sm = Mm;
        #pragma unroll
        for (int d = 1; d < 32; d <<= 1) {
            unsigned dn = __shfl_down_sync(~0u, Sm, d);
            if (lane + d < 32) Sm = compose(Sm, dn);
        }
        unsigned Em = __shfl_down_sync(~0u, Sm, 1);
        if (lane == 31) Em = IDMAP;
        if (lane == 0) sMv[wid] = Sm;
        __syncthreads();

        unsigned X = IDMAP;
        #pragma unroll
        for (int w2 = 0; w2 < 8; w2++)
            if (w2 > wid) X = compose(X, sMv[w2]);
        unsigned Efull = compose(Em, X);
        int last = s_last;
        int t1 = (Efull >> (8 * last)) & 3;
        int t0 = (bp[1] >> (8 * t1)) & 3;
        float* po = out + OFF_CRF + b * SS + tid * 2;
        po[1] = (float)t1;
        po[0] = (float)t0;
    }

    // ---------- finalize (last CRF block) + resets for next replay ----------
    __syncthreads();
    __threadfence();
    if (wid == 0) {
        int ticket = 0;
        if (lane == 0) ticket = atomicAdd(&g_done, 1);
        ticket = __shfl_sync(~0u, ticket, 0);
        if (ticket == 127) {
            float il = 0.f, cl = 0.f;
            #pragma unroll
            for (int q = 0; q < 2; q++) {
                int bi = lane * 2 + q;       // 0..63, in bounds
                float l0 = g_logits[bi * 2 + 0];
                float l1 = g_logits[bi * 2 + 1];
                float m = fmaxf(l0, l1);
                float lse = m + __logf(__expf(l0 - m) + __expf(l1 - m));
                int iq = isqa_in[bi];
                il += lse - (iq ? l1 : l0);
                cl += g_Z[bi] - g_gold[bi];
                out[OFF_PRED + bi] = (l1 > l0) ? 1.0f : 0.0f;
                out[OFF_ISQA + bi] = (float)iq;
                g_ready[bi] = 0;
            }
            #pragma unroll
            for (int off = 16; off; off >>= 1) {
                il += __shfl_xor_sync(~0u, il, off);
                cl += __shfl_xor_sync(~0u, cl, off);
            }
            if (lane == 0) {
                out[OFF_ILOSS] = il * (1.0f / BB);
                out[OFF_CLOSS] = cl * (1.0f / BB);
                g_done = 0;
            }
        }
    }
}

extern "C" void kernel_launch(void* const* d_in, const int* in_sizes, int n_in,
                              void* d_out, int out_size)
{
    const float* emb  = (const float*)d_in[0];
    const int*   asl  = (const int*)d_in[1];
    const int*   isqa = (const int*)d_in[2];
    const float* fc2W = (const float*)d_in[3];
    const float* fc2b = (const float*)d_in[4];
    const float* crfW = (const float*)d_in[5];
    const float* crfb = (const float*)d_in[6];
    const float* trans = (const float*)d_in[7];
    float* out = (float*)d_out;

    k_all<<<FEATS_BLOCKS + 128, 256>>>(emb, asl, isqa, fc2W, fc2b,
                                       crfW, crfb, trans, out);
}